// round 2
// baseline (speedup 1.0000x reference)
#include <cuda_runtime.h>

#define NN 50000
#define NE 800000
#define LD 128
#define FED 32
#define TR 64
#define NT 256
#define NB_NODE ((NN + TR - 1) / TR)
#define NB_EDGE (NE / TR)

// Scratch (device globals: allocation is banned)
__device__ float g_inl[NN * LD];        // node linear features
__device__ float g_im[NE * LD];         // input_message
__device__ float g_curW[NE * LD];       // cur @ conv_W
__device__ float g_agg[NN * LD];        // segment-sum accumulator
__device__ float g_aggW[NN * LD];       // node_agg @ conv_W

__device__ __forceinline__ float4 relu4(float4 v) {
    v.x = fmaxf(v.x, 0.f); v.y = fmaxf(v.y, 0.f);
    v.z = fmaxf(v.z, 0.f); v.w = fmaxf(v.w, 0.f);
    return v;
}

__device__ __forceinline__ void red_add4(float* p, float4 v) {
    asm volatile("red.global.add.v4.f32 [%0], {%1,%2,%3,%4};"
                 :: "l"(p), "f"(v.x), "f"(v.y), "f"(v.z), "f"(v.w) : "memory");
}

// 64x128 = (64x128 @ 128x128) tile GEMM. 256 threads, each 8 rows x 4 cols.
__device__ __forceinline__ void gemm_tile128(const float* __restrict__ x_s,
                                             const float* __restrict__ w_s,
                                             float acc[8][4], int tx, int ty) {
#pragma unroll 4
    for (int k = 0; k < LD; k++) {
        float4 b = reinterpret_cast<const float4*>(w_s + k * LD)[tx];
#pragma unroll
        for (int i = 0; i < 8; i++) {
            float a = x_s[(ty * 8 + i) * LD + k];
            acc[i][0] = fmaf(a, b.x, acc[i][0]);
            acc[i][1] = fmaf(a, b.y, acc[i][1]);
            acc[i][2] = fmaf(a, b.z, acc[i][2]);
            acc[i][3] = fmaf(a, b.w, acc[i][3]);
        }
    }
}

__global__ void k_zero(float* out, int out_n) {
    int stride = gridDim.x * blockDim.x;
    for (int i = blockIdx.x * blockDim.x + threadIdx.x; i < NN * LD; i += stride)
        g_agg[i] = 0.f;
    for (int i = blockIdx.x * blockDim.x + threadIdx.x; i < out_n; i += stride)
        out[i] = 0.f;
}

// g_inl = node_feat @ Wn + bn
__global__ void __launch_bounds__(NT, 2)
k_node_linear(const float* __restrict__ nf, const float* __restrict__ W,
              const float* __restrict__ bias) {
    extern __shared__ float sm[];
    float* w_s = sm;                 // 128*128
    float* x_s = sm + LD * LD;       // 64*128
    float* b_s = x_s + TR * LD;      // 128
    int tid = threadIdx.x;
    int row0 = blockIdx.x * TR;

    for (int i = tid; i < LD * LD / 4; i += NT)
        reinterpret_cast<float4*>(w_s)[i] = reinterpret_cast<const float4*>(W)[i];
    if (tid < LD / 4)
        reinterpret_cast<float4*>(b_s)[tid] = reinterpret_cast<const float4*>(bias)[tid];
    for (int i = tid; i < TR * (LD / 4); i += NT) {
        int r = i >> 5, c4 = i & 31;
        int n = row0 + r;
        float4 v = make_float4(0.f, 0.f, 0.f, 0.f);
        if (n < NN) v = reinterpret_cast<const float4*>(nf + (long)n * LD)[c4];
        reinterpret_cast<float4*>(x_s + r * LD)[c4] = v;
    }
    __syncthreads();

    int tx = tid & 31, ty = tid >> 5;
    float acc[8][4] = {};
    gemm_tile128(x_s, w_s, acc, tx, ty);
    float4 bb = reinterpret_cast<const float4*>(b_s)[tx];
#pragma unroll
    for (int i = 0; i < 8; i++) {
        int n = row0 + ty * 8 + i;
        if (n < NN) {
            float4 o = make_float4(acc[i][0] + bb.x, acc[i][1] + bb.y,
                                   acc[i][2] + bb.z, acc[i][3] + bb.w);
            reinterpret_cast<float4*>(g_inl + (long)n * LD)[tx] = o;
        }
    }
}

// g_aggW = g_agg @ Wc ; then g_agg := 0 (ready for next scatter)
__global__ void __launch_bounds__(NT, 2)
k_node_aggW(const float* __restrict__ Wc) {
    extern __shared__ float sm[];
    float* w_s = sm;
    float* x_s = sm + LD * LD;
    int tid = threadIdx.x;
    int row0 = blockIdx.x * TR;

    for (int i = tid; i < LD * LD / 4; i += NT)
        reinterpret_cast<float4*>(w_s)[i] = reinterpret_cast<const float4*>(Wc)[i];
    const float4 z4 = make_float4(0.f, 0.f, 0.f, 0.f);
    for (int i = tid; i < TR * (LD / 4); i += NT) {
        int r = i >> 5, c4 = i & 31;
        int n = row0 + r;
        float4 v = z4;
        if (n < NN) {
            v = reinterpret_cast<const float4*>(g_agg + (long)n * LD)[c4];
            reinterpret_cast<float4*>(g_agg + (long)n * LD)[c4] = z4;
        }
        reinterpret_cast<float4*>(x_s + r * LD)[c4] = v;
    }
    __syncthreads();

    int tx = tid & 31, ty = tid >> 5;
    float acc[8][4] = {};
    gemm_tile128(x_s, w_s, acc, tx, ty);
#pragma unroll
    for (int i = 0; i < 8; i++) {
        int n = row0 + ty * 8 + i;
        if (n < NN)
            reinterpret_cast<float4*>(g_aggW + (long)n * LD)[tx] =
                make_float4(acc[i][0], acc[i][1], acc[i][2], acc[i][3]);
    }
}

// Prologue per edge tile: im = inl[src] + ef@We + be ; x = relu(im);
// g_curW = x @ Wc ; g_agg[dst] += x
__global__ void __launch_bounds__(NT)
k_im(const float* __restrict__ ef, const float* __restrict__ We,
     const float* __restrict__ be, const float* __restrict__ Wc,
     const int* __restrict__ esrc, const int* __restrict__ edst) {
    extern __shared__ float sm[];
    float* w_s  = sm;                          // conv_W 128*128
    float* we_s = w_s + LD * LD;               // 32*128
    float* x_s  = we_s + FED * LD;             // 64*128
    float* ef_s = x_s + TR * LD;               // 64*32
    float* be_s = ef_s + TR * FED;             // 128
    int* src_s  = reinterpret_cast<int*>(be_s + LD);
    int* dst_s  = src_s + TR;
    int tid = threadIdx.x;
    int row0 = blockIdx.x * TR;

    for (int i = tid; i < LD * LD / 4; i += NT)
        reinterpret_cast<float4*>(w_s)[i] = reinterpret_cast<const float4*>(Wc)[i];
    for (int i = tid; i < FED * LD / 4; i += NT)
        reinterpret_cast<float4*>(we_s)[i] = reinterpret_cast<const float4*>(We)[i];
    for (int i = tid; i < TR * FED / 4; i += NT)
        reinterpret_cast<float4*>(ef_s)[i] =
            reinterpret_cast<const float4*>(ef + (long)row0 * FED)[i];
    if (tid < LD / 4)
        reinterpret_cast<float4*>(be_s)[tid] = reinterpret_cast<const float4*>(be)[tid];
    if (tid < TR) src_s[tid] = esrc[row0 + tid];
    else if (tid < 2 * TR) dst_s[tid - TR] = edst[row0 + tid - TR];
    __syncthreads();

#pragma unroll
    for (int ii = 0; ii < 8; ii++) {
        int j = tid + NT * ii;          // warp-uniform row, lane = c4
        int r = j >> 5, c4 = j & 31;
        int e = row0 + r;
        float4 a = reinterpret_cast<const float4*>(g_inl + (long)src_s[r] * LD)[c4];
        float4 bb = reinterpret_cast<const float4*>(be_s)[c4];
        float4 acc = make_float4(a.x + bb.x, a.y + bb.y, a.z + bb.z, a.w + bb.w);
#pragma unroll
        for (int k = 0; k < FED; k++) {
            float s = ef_s[r * FED + k];
            float4 wv = reinterpret_cast<const float4*>(we_s + k * LD)[c4];
            acc.x = fmaf(s, wv.x, acc.x); acc.y = fmaf(s, wv.y, acc.y);
            acc.z = fmaf(s, wv.z, acc.z); acc.w = fmaf(s, wv.w, acc.w);
        }
        reinterpret_cast<float4*>(g_im + (long)e * LD)[c4] = acc;
        float4 x = relu4(acc);
        reinterpret_cast<float4*>(x_s + r * LD)[c4] = x;
        red_add4(g_agg + (long)dst_s[r] * LD + c4 * 4, x);
    }
    __syncthreads();

    int tx = tid & 31, ty = tid >> 5;
    float acc[8][4] = {};
    gemm_tile128(x_s, w_s, acc, tx, ty);
#pragma unroll
    for (int i = 0; i < 8; i++) {
        int e = row0 + ty * 8 + i;
        reinterpret_cast<float4*>(g_curW + (long)e * LD)[tx] =
            make_float4(acc[i][0], acc[i][1], acc[i][2], acc[i][3]);
    }
}

// One BP iteration per edge tile:
// x = relu(aggW[src] - curW[e^1] + im + bc) ; agg[dst] += x ; curW = x @ Wc (unless last)
__global__ void __launch_bounds__(NT, 2)
k_iter(const float* __restrict__ Wc, const float* __restrict__ bc,
       const int* __restrict__ esrc, const int* __restrict__ edst, int last) {
    extern __shared__ float sm[];
    float* w_s = sm;
    float* x_s = sm + LD * LD;
    float* b_s = x_s + TR * LD;
    int* src_s = reinterpret_cast<int*>(b_s + LD);
    int* dst_s = src_s + TR;
    int tid = threadIdx.x;
    int row0 = blockIdx.x * TR;

    for (int i = tid; i < LD * LD / 4; i += NT)
        reinterpret_cast<float4*>(w_s)[i] = reinterpret_cast<const float4*>(Wc)[i];
    if (tid < LD / 4)
        reinterpret_cast<float4*>(b_s)[tid] = reinterpret_cast<const float4*>(bc)[tid];
    if (tid < TR) src_s[tid] = esrc[row0 + tid];
    else if (tid < 2 * TR) dst_s[tid - TR] = edst[row0 + tid - TR];
    __syncthreads();

#pragma unroll
    for (int ii = 0; ii < 8; ii++) {
        int j = tid + NT * ii;
        int r = j >> 5, c4 = j & 31;
        int e = row0 + r;
        int erev = e ^ 1;               // reverse edge lives in this tile
        float4 aw = reinterpret_cast<const float4*>(g_aggW + (long)src_s[r] * LD)[c4];
        float4 cw = reinterpret_cast<const float4*>(g_curW + (long)erev * LD)[c4];
        float4 im = reinterpret_cast<const float4*>(g_im + (long)e * LD)[c4];
        float4 bb = reinterpret_cast<const float4*>(b_s)[c4];
        float4 x;
        x.x = fmaxf(aw.x - cw.x + im.x + bb.x, 0.f);
        x.y = fmaxf(aw.y - cw.y + im.y + bb.y, 0.f);
        x.z = fmaxf(aw.z - cw.z + im.z + bb.z, 0.f);
        x.w = fmaxf(aw.w - cw.w + im.w + bb.w, 0.f);
        reinterpret_cast<float4*>(x_s + r * LD)[c4] = x;
        red_add4(g_agg + (long)dst_s[r] * LD + c4 * 4, x);
    }
    __syncthreads();   // all curW reads done; all x_s written

    if (!last) {
        int tx = tid & 31, ty = tid >> 5;
        float acc[8][4] = {};
        gemm_tile128(x_s, w_s, acc, tx, ty);
#pragma unroll
        for (int i = 0; i < 8; i++) {
            int e = row0 + ty * 8 + i;
            reinterpret_cast<float4*>(g_curW + (long)e * LD)[tx] =
                make_float4(acc[i][0], acc[i][1], acc[i][2], acc[i][3]);
        }
    }
}

// Epilogue: h = relu(agg) ; y = relu(h @ Wo + bo) ; out[graph] += y
__global__ void __launch_bounds__(NT, 2)
k_out(const float* __restrict__ Wo, const float* __restrict__ bo,
      const int* __restrict__ gids, float* __restrict__ out) {
    extern __shared__ float sm[];
    float* w_s = sm;
    float* x_s = sm + LD * LD;
    float* b_s = x_s + TR * LD;
    int* gid_s = reinterpret_cast<int*>(b_s + LD);
    int tid = threadIdx.x;
    int row0 = blockIdx.x * TR;

    for (int i = tid; i < LD * LD / 4; i += NT)
        reinterpret_cast<float4*>(w_s)[i] = reinterpret_cast<const float4*>(Wo)[i];
    if (tid < LD / 4)
        reinterpret_cast<float4*>(b_s)[tid] = reinterpret_cast<const float4*>(bo)[tid];
    if (tid < TR) {
        int n = row0 + tid;
        gid_s[tid] = (n < NN) ? gids[n] : 0;
    }
    for (int i = tid; i < TR * (LD / 4); i += NT) {
        int r = i >> 5, c4 = i & 31;
        int n = row0 + r;
        float4 v = make_float4(0.f, 0.f, 0.f, 0.f);
        if (n < NN)
            v = relu4(reinterpret_cast<const float4*>(g_agg + (long)n * LD)[c4]);
        reinterpret_cast<float4*>(x_s + r * LD)[c4] = v;
    }
    __syncthreads();

    int tx = tid & 31, ty = tid >> 5;
    float acc[8][4] = {};
    gemm_tile128(x_s, w_s, acc, tx, ty);
    float4 bb = reinterpret_cast<const float4*>(b_s)[tx];
#pragma unroll
    for (int i = 0; i < 8; i++) {
        int r = ty * 8 + i;
        int n = row0 + r;
        if (n < NN) {
            float4 y = make_float4(fmaxf(acc[i][0] + bb.x, 0.f),
                                   fmaxf(acc[i][1] + bb.y, 0.f),
                                   fmaxf(acc[i][2] + bb.z, 0.f),
                                   fmaxf(acc[i][3] + bb.w, 0.f));
            red_add4(out + (long)gid_s[r] * LD + tx * 4, y);
        }
    }
}

extern "C" void kernel_launch(void* const* d_in, const int* in_sizes, int n_in,
                              void* d_out, int out_size) {
    const float* node_feat = (const float*)d_in[0];
    const float* edge_feat = (const float*)d_in[1];
    const float* Wn = (const float*)d_in[2];
    const float* bn = (const float*)d_in[3];
    const float* We = (const float*)d_in[4];
    const float* be = (const float*)d_in[5];
    const float* Wc = (const float*)d_in[6];
    const float* bc = (const float*)d_in[7];
    const float* Wo = (const float*)d_in[8];
    const float* bo = (const float*)d_in[9];
    const int* esrc = (const int*)d_in[10];
    const int* edst = (const int*)d_in[11];
    const int* gids = (const int*)d_in[12];
    float* out = (float*)d_out;

    const int SM_NODE = (LD * LD + TR * LD + LD) * 4;            // 98816
    const int SM_ITER = SM_NODE + 2 * TR * 4;                    // 99328
    const int SM_IM   = (LD * LD + FED * LD + TR * LD + TR * FED + LD) * 4 + 2 * TR * 4;
    const int SM_OUT  = SM_NODE + TR * 4;                        // 99072

    cudaFuncSetAttribute(k_node_linear, cudaFuncAttributeMaxDynamicSharedMemorySize, SM_NODE);
    cudaFuncSetAttribute(k_node_aggW,   cudaFuncAttributeMaxDynamicSharedMemorySize, SM_NODE);
    cudaFuncSetAttribute(k_im,          cudaFuncAttributeMaxDynamicSharedMemorySize, SM_IM);
    cudaFuncSetAttribute(k_iter,        cudaFuncAttributeMaxDynamicSharedMemorySize, SM_ITER);
    cudaFuncSetAttribute(k_out,         cudaFuncAttributeMaxDynamicSharedMemorySize, SM_OUT);

    k_zero<<<384, 256>>>(out, out_size);
    k_node_linear<<<NB_NODE, NT, SM_NODE>>>(node_feat, Wn, bn);
    k_im<<<NB_EDGE, NT, SM_IM>>>(edge_feat, We, be, Wc, esrc, edst);
    for (int t = 0; t < 3; t++) {
        k_node_aggW<<<NB_NODE, NT, SM_NODE>>>(Wc);
        k_iter<<<NB_EDGE, NT, SM_ITER>>>(Wc, bc, esrc, edst, (t == 2) ? 1 : 0);
    }
    k_out<<<NB_NODE, NT, SM_OUT>>>(Wo, bo, gids, out);
}

// round 4
// speedup vs baseline: 1.3518x; 1.3518x over previous
#include <cuda_runtime.h>
#include <cuda_bf16.h>
#include <cstdint>

#define NN 50000
#define NE 800000

// ---------------- scratch ----------------
__device__ float g_inl[NN * 128];
__device__ float g_im[NE * 128];
__device__ float g_curW[NE * 128];
__device__ float g_agg[NN * 128];
__device__ float g_aggW[NN * 128];
// bf16 weight tables: W^T layout [oc][k], hi table then lo table
__device__ uint16_t g_wc[2 * 16384];
__device__ uint16_t g_wn[2 * 16384];
__device__ uint16_t g_wo[2 * 16384];
__device__ uint16_t g_we[2 * 4096];   // [oc=128][k=32]

#define XSTRIDE 132                     // u32 per smem row (conflict-free ldmatrix)
#define LO_OFF (128 * 132)              // u32 offset of lo region
#define SMEM_BYTES (2 * 128 * 132 * 4)  // 135168 B

// ---------------- helpers ----------------
__device__ __forceinline__ uint32_t smem_u32(const void* p) {
    uint32_t a;
    asm("{ .reg .u64 t; cvta.to.shared.u64 t, %1; cvt.u32.u64 %0, t; }" : "=r"(a) : "l"(p));
    return a;
}
__device__ __forceinline__ void ldm4(uint32_t* r, uint32_t addr) {
    asm volatile("ldmatrix.sync.aligned.m8n8.x4.shared.b16 {%0,%1,%2,%3}, [%4];"
                 : "=r"(r[0]), "=r"(r[1]), "=r"(r[2]), "=r"(r[3]) : "r"(addr));
}
__device__ __forceinline__ void mma_bf16(float* d, const uint32_t* a, uint32_t b0, uint32_t b1) {
    asm volatile("mma.sync.aligned.m16n8k16.row.col.f32.bf16.bf16.f32 "
                 "{%0,%1,%2,%3}, {%4,%5,%6,%7}, {%8,%9}, {%0,%1,%2,%3};"
                 : "+f"(d[0]), "+f"(d[1]), "+f"(d[2]), "+f"(d[3])
                 : "r"(a[0]), "r"(a[1]), "r"(a[2]), "r"(a[3]), "r"(b0), "r"(b1));
}
__device__ __forceinline__ float4 relu4(float4 v) {
    v.x = fmaxf(v.x, 0.f); v.y = fmaxf(v.y, 0.f);
    v.z = fmaxf(v.z, 0.f); v.w = fmaxf(v.w, 0.f);
    return v;
}
__device__ __forceinline__ void red_add4(float* p, float4 v) {
    asm volatile("red.global.add.v4.f32 [%0], {%1,%2,%3,%4};"
                 :: "l"(p), "f"(v.x), "f"(v.y), "f"(v.z), "f"(v.w) : "memory");
}
__device__ __forceinline__ uint32_t pck(float a, float b) {   // low=a, high=b
    uint32_t r;
    asm("cvt.rn.bf16x2.f32 %0, %1, %2;" : "=r"(r) : "f"(b), "f"(a));
    return r;
}
__device__ __forceinline__ void split_f4(float4 v, uint32_t& h0, uint32_t& h1,
                                         uint32_t& l0, uint32_t& l1) {
    h0 = pck(v.x, v.y); h1 = pck(v.z, v.w);
    float a0 = __uint_as_float(h0 << 16);
    float a1 = __uint_as_float(h0 & 0xFFFF0000u);
    float a2 = __uint_as_float(h1 << 16);
    float a3 = __uint_as_float(h1 & 0xFFFF0000u);
    l0 = pck(v.x - a0, v.y - a1);
    l1 = pck(v.z - a2, v.w - a3);
}

// D^T[oc][n] = W^T X^T with hi/lo split; X in smem (hi @0, lo @BLO rel. pattern),
// W frags from global tables. Stages result into sout[n*XSTRIDE + oc] (f32).
// NKT: K/16 tiles. WS: u32 stride per W-table row. BLO: u32 offset of B-lo matrices.
template <int NKT, int WS, int BLO>
__device__ __forceinline__ void mma_stage(uint32_t sb, const uint32_t* w2h,
                                          const uint32_t* w2l, float* sout,
                                          int warp, int lane) {
    int q = lane >> 2, m4 = lane & 3;
    int oc = warp * 16 + q;
    uint32_t ah[NKT][4], al[NKT][4];
#pragma unroll
    for (int kt = 0; kt < NKT; kt++) {
        int b0 = oc * WS + kt * 8 + m4, b1 = (oc + 8) * WS + kt * 8 + m4;
        ah[kt][0] = w2h[b0];     ah[kt][1] = w2h[b1];
        ah[kt][2] = w2h[b0 + 4]; ah[kt][3] = w2h[b1 + 4];
        al[kt][0] = w2l[b0];     al[kt][1] = w2l[b1];
        al[kt][2] = w2l[b0 + 4]; al[kt][3] = w2l[b1 + 4];
    }
    float acc[16][4];
#pragma unroll
    for (int nt = 0; nt < 16; nt++)
#pragma unroll
        for (int i = 0; i < 4; i++) acc[nt][i] = 0.f;

    int j8 = lane & 7, sel = lane >> 3;
    uint32_t aoff = (sel >= 2 ? (uint32_t)BLO : 0u) + (uint32_t)j8 * XSTRIDE + (sel & 1) * 4;
#pragma unroll
    for (int kt = 0; kt < NKT; kt++) {
#pragma unroll
        for (int nt = 0; nt < 16; nt++) {
            uint32_t b[4];
            ldm4(b, sb + (aoff + (uint32_t)nt * 8 * XSTRIDE + (uint32_t)kt * 8) * 4);
            mma_bf16(acc[nt], ah[kt], b[0], b[1]);   // Wh * Xh
            mma_bf16(acc[nt], al[kt], b[0], b[1]);   // Wl * Xh
            mma_bf16(acc[nt], ah[kt], b[2], b[3]);   // Wh * Xl
        }
    }
    __syncthreads();   // all B reads done before staging overwrites X region
#pragma unroll
    for (int nt = 0; nt < 16; nt++) {
        int e = nt * 8 + m4 * 2;
        sout[e * XSTRIDE + oc]           = acc[nt][0];
        sout[(e + 1) * XSTRIDE + oc]     = acc[nt][1];
        sout[e * XSTRIDE + oc + 8]       = acc[nt][2];
        sout[(e + 1) * XSTRIDE + oc + 8] = acc[nt][3];
    }
    __syncthreads();
}

// ---------------- prep / zero ----------------
__global__ void k_prep(const float* __restrict__ Wc, const float* __restrict__ Wn,
                       const float* __restrict__ Wo, const float* __restrict__ We) {
    int st = gridDim.x * blockDim.x;
    for (int idx = blockIdx.x * blockDim.x + threadIdx.x; idx < 16384; idx += st) {
        int k = idx >> 7, n = idx & 127;
        int pos = n * 128 + k;   // [oc][k]
        float v;
        __nv_bfloat16 hb;
        v = Wc[idx]; hb = __float2bfloat16_rn(v);
        g_wc[pos] = __bfloat16_as_ushort(hb);
        g_wc[16384 + pos] = __bfloat16_as_ushort(__float2bfloat16_rn(v - __bfloat162float(hb)));
        v = Wn[idx]; hb = __float2bfloat16_rn(v);
        g_wn[pos] = __bfloat16_as_ushort(hb);
        g_wn[16384 + pos] = __bfloat16_as_ushort(__float2bfloat16_rn(v - __bfloat162float(hb)));
        v = Wo[idx]; hb = __float2bfloat16_rn(v);
        g_wo[pos] = __bfloat16_as_ushort(hb);
        g_wo[16384 + pos] = __bfloat16_as_ushort(__float2bfloat16_rn(v - __bfloat162float(hb)));
    }
    for (int idx = blockIdx.x * blockDim.x + threadIdx.x; idx < 4096; idx += st) {
        int k = idx >> 7, n = idx & 127;      // k 0..31
        float v = We[k * 128 + n];
        __nv_bfloat16 hb = __float2bfloat16_rn(v);
        g_we[n * 32 + k] = __bfloat16_as_ushort(hb);
        g_we[4096 + n * 32 + k] =
            __bfloat16_as_ushort(__float2bfloat16_rn(v - __bfloat162float(hb)));
    }
}
__global__ void k_zero(float* out, int out_n) {
    int i = blockIdx.x * blockDim.x + threadIdx.x, st = gridDim.x * blockDim.x;
    float4 z = make_float4(0.f, 0.f, 0.f, 0.f);
    for (int j = i; j < NN * 32; j += st) reinterpret_cast<float4*>(g_agg)[j] = z;
    for (int j = i; j < out_n; j += st) out[j] = 0.f;
}

// write x (16 float4 of row r, half h) split into smem hi/lo regions
__device__ __forceinline__ void xwrite(uint8_t* sm, int r, int h, const float4* x) {
    uint32_t* xh = reinterpret_cast<uint32_t*>(sm) + r * XSTRIDE + h * 32;
    uint32_t* xl = reinterpret_cast<uint32_t*>(sm) + LO_OFF + r * XSTRIDE + h * 32;
#pragma unroll
    for (int j = 0; j < 16; j++) {
        uint32_t h0, h1, l0, l1;
        split_f4(x[j], h0, h1, l0, l1);
        xh[2 * j] = h0; xh[2 * j + 1] = h1;
        xl[2 * j] = l0; xl[2 * j + 1] = l1;
    }
}

// ---------------- edge kernels ----------------
__global__ void __launch_bounds__(256)
k_first(const float* __restrict__ ef, const float* __restrict__ be,
        const float* __restrict__ esrc_f, const int* __restrict__ esrc,
        const int* __restrict__ edst) {
    extern __shared__ uint8_t sm[];
    uint32_t sb = smem_u32(sm);
    int t = threadIdx.x, r = t >> 1, h = t & 1;
    int e = blockIdx.x * 128 + r;
    int src = esrc[e], dst = edst[e];
    int warp = t >> 5, lane = t & 31;

    // phase 0: split edge_feat rows into smem (hi cols 0..15 u32, lo at +16)
    {
        const float4* efp = reinterpret_cast<const float4*>(ef + (size_t)e * 32 + h * 16);
        uint32_t* eh = reinterpret_cast<uint32_t*>(sm) + r * XSTRIDE + h * 8;
        uint32_t* el = reinterpret_cast<uint32_t*>(sm) + r * XSTRIDE + 16 + h * 8;
#pragma unroll
        for (int j = 0; j < 4; j++) {
            uint32_t h0, h1, l0, l1;
            split_f4(efp[j], h0, h1, l0, l1);
            eh[2 * j] = h0; eh[2 * j + 1] = h1;
            el[2 * j] = l0; el[2 * j + 1] = l1;
        }
    }
    __syncthreads();
    float* s1 = reinterpret_cast<float*>(sm) + LO_OFF;   // stage D1 in lo region
    mma_stage<2, 16, 16>(sb, reinterpret_cast<const uint32_t*>(g_we),
                         reinterpret_cast<const uint32_t*>(g_we) + 2048, s1, warp, lane);

    // phase 1: im = D1 + inl[src] + be ; x = relu(im)
    float4 x[16];
    {
        const float4* d1 = reinterpret_cast<const float4*>(s1 + r * XSTRIDE + h * 64);
        const float4* il = reinterpret_cast<const float4*>(g_inl + (size_t)src * 128 + h * 64);
        const float4* bp = reinterpret_cast<const float4*>(be + h * 64);
        float4* imo = reinterpret_cast<float4*>(g_im + (size_t)e * 128 + h * 64);
#pragma unroll
        for (int j = 0; j < 16; j++) {
            float4 d = d1[j], a = il[j], b = bp[j];
            float4 m = make_float4(d.x + a.x + b.x, d.y + a.y + b.y,
                                   d.z + a.z + b.z, d.w + a.w + b.w);
            imo[j] = m;
            x[j] = relu4(m);
        }
    }
    __syncthreads();   // all D1 reads complete before lo region is overwritten
    xwrite(sm, r, h, x);
    {
        float* aggp = g_agg + (size_t)dst * 128 + h * 64;
#pragma unroll
        for (int j = 0; j < 16; j++) red_add4(aggp + 4 * j, x[j]);
    }
    __syncthreads();
    mma_stage<8, 64, LO_OFF>(sb, reinterpret_cast<const uint32_t*>(g_wc),
                             reinterpret_cast<const uint32_t*>(g_wc) + 8192,
                             reinterpret_cast<float*>(sm), warp, lane);
    {
        const float4* s4 = reinterpret_cast<const float4*>(
            reinterpret_cast<float*>(sm) + r * XSTRIDE + h * 64);
        float4* cw = reinterpret_cast<float4*>(g_curW + (size_t)e * 128 + h * 64);
#pragma unroll
        for (int j = 0; j < 16; j++) cw[j] = s4[j];
    }
}

__global__ void __launch_bounds__(256)
k_iter(const float* __restrict__ bc, const int* __restrict__ esrc,
       const int* __restrict__ edst) {
    extern __shared__ uint8_t sm[];
    uint32_t sb = smem_u32(sm);
    int t = threadIdx.x, r = t >> 1, h = t & 1;
    int e = blockIdx.x * 128 + r;
    int src = esrc[e], dst = edst[e];
    {
        const float4* aw = reinterpret_cast<const float4*>(g_aggW + (size_t)src * 128 + h * 64);
        const float4* cw = reinterpret_cast<const float4*>(g_curW + (size_t)(e ^ 1) * 128 + h * 64);
        const float4* im = reinterpret_cast<const float4*>(g_im + (size_t)e * 128 + h * 64);
        const float4* bp = reinterpret_cast<const float4*>(bc + h * 64);
        float* aggp = g_agg + (size_t)dst * 128 + h * 64;
        float4 x[16];
#pragma unroll
        for (int j = 0; j < 16; j++) {
            float4 a = aw[j], c = cw[j], m = im[j], b = bp[j];
            float4 v = make_float4(a.x - c.x + m.x + b.x, a.y - c.y + m.y + b.y,
                                   a.z - c.z + m.z + b.z, a.w - c.w + m.w + b.w);
            x[j] = relu4(v);
        }
        xwrite(sm, r, h, x);
#pragma unroll
        for (int j = 0; j < 16; j++) red_add4(aggp + 4 * j, x[j]);
    }
    __syncthreads();
    int warp = t >> 5, lane = t & 31;
    mma_stage<8, 64, LO_OFF>(sb, reinterpret_cast<const uint32_t*>(g_wc),
                             reinterpret_cast<const uint32_t*>(g_wc) + 8192,
                             reinterpret_cast<float*>(sm), warp, lane);
    {
        const float4* s4 = reinterpret_cast<const float4*>(
            reinterpret_cast<float*>(sm) + r * XSTRIDE + h * 64);
        float4* cw = reinterpret_cast<float4*>(g_curW + (size_t)e * 128 + h * 64);
#pragma unroll
        for (int j = 0; j < 16; j++) cw[j] = s4[j];
    }
}

// last iteration: only x + scatter (no curW / GEMM)
__global__ void __launch_bounds__(256)
k_last(const float* __restrict__ bc, const int* __restrict__ esrc,
       const int* __restrict__ edst) {
    int t = threadIdx.x, r = t >> 1, h = t & 1;
    int e = blockIdx.x * 128 + r;
    int src = esrc[e], dst = edst[e];
    const float4* aw = reinterpret_cast<const float4*>(g_aggW + (size_t)src * 128 + h * 64);
    const float4* cw = reinterpret_cast<const float4*>(g_curW + (size_t)(e ^ 1) * 128 + h * 64);
    const float4* im = reinterpret_cast<const float4*>(g_im + (size_t)e * 128 + h * 64);
    const float4* bp = reinterpret_cast<const float4*>(bc + h * 64);
    float* aggp = g_agg + (size_t)dst * 128 + h * 64;
#pragma unroll
    for (int j = 0; j < 16; j++) {
        float4 a = aw[j], c = cw[j], m = im[j], b = bp[j];
        float4 v = make_float4(a.x - c.x + m.x + b.x, a.y - c.y + m.y + b.y,
                               a.z - c.z + m.z + b.z, a.w - c.w + m.w + b.w);
        red_add4(aggp + 4 * j, relu4(v));
    }
}

// ---------------- node kernels ----------------
__global__ void __launch_bounds__(256)
k_nlin(const float* __restrict__ nf, const float* __restrict__ bn) {
    extern __shared__ uint8_t sm[];
    uint32_t sb = smem_u32(sm);
    int t = threadIdx.x, r = t >> 1, h = t & 1;
    int n = blockIdx.x * 128 + r;
    bool v = n < NN;
    int nc = v ? n : 0;
    {
        const float4* xp = reinterpret_cast<const float4*>(nf + (size_t)nc * 128 + h * 64);
        float4 x[16];
#pragma unroll
        for (int j = 0; j < 16; j++) x[j] = xp[j];
        xwrite(sm, r, h, x);
    }
    __syncthreads();
    int warp = t >> 5, lane = t & 31;
    mma_stage<8, 64, LO_OFF>(sb, reinterpret_cast<const uint32_t*>(g_wn),
                             reinterpret_cast<const uint32_t*>(g_wn) + 8192,
                             reinterpret_cast<float*>(sm), warp, lane);
    if (v) {
        const float4* s4 = reinterpret_cast<const float4*>(
            reinterpret_cast<float*>(sm) + r * XSTRIDE + h * 64);
        const float4* bp = reinterpret_cast<const float4*>(bn + h * 64);
        float4* o = reinterpret_cast<float4*>(g_inl + (size_t)n * 128 + h * 64);
#pragma unroll
        for (int j = 0; j < 16; j++) {
            float4 s = s4[j], b = bp[j];
            o[j] = make_float4(s.x + b.x, s.y + b.y, s.z + b.z, s.w + b.w);
        }
    }
}

__global__ void __launch_bounds__(256)
k_aggW() {
    extern __shared__ uint8_t sm[];
    uint32_t sb = smem_u32(sm);
    int t = threadIdx.x, r = t >> 1, h = t & 1;
    int n = blockIdx.x * 128 + r;
    bool v = n < NN;
    int nc = v ? n : 0;
    {
        float4* ap = reinterpret_cast<float4*>(g_agg + (size_t)nc * 128 + h * 64);
        const float4 z = make_float4(0.f, 0.f, 0.f, 0.f);
        float4 x[16];
#pragma unroll
        for (int j = 0; j < 16; j++) {
            x[j] = ap[j];
            if (v) ap[j] = z;   // reset for next scatter round
        }
        xwrite(sm, r, h, x);
    }
    __syncthreads();
    int warp = t >> 5, lane = t & 31;
    mma_stage<8, 64, LO_OFF>(sb, reinterpret_cast<const uint32_t*>(g_wc),
                             reinterpret_cast<const uint32_t*>(g_wc) + 8192,
                             reinterpret_cast<float*>(sm), warp, lane);
    if (v) {
        const float4* s4 = reinterpret_cast<const float4*>(
            reinterpret_cast<float*>(sm) + r * XSTRIDE + h * 64);
        float4* o = reinterpret_cast<float4*>(g_aggW + (size_t)n * 128 + h * 64);
#pragma unroll
        for (int j = 0; j < 16; j++) o[j] = s4[j];
    }
}

__global__ void __launch_bounds__(256)
k_out(const float* __restrict__ bo, const int* __restrict__ gids,
      float* __restrict__ out) {
    extern __shared__ uint8_t sm[];
    uint32_t sb = smem_u32(sm);
    int t = threadIdx.x, r = t >> 1, h = t & 1;
    int n = blockIdx.x * 128 + r;
    bool v = n < NN;
    int nc = v ? n : 0;
    {
        const float4* ap = reinterpret_cast<const float4*>(g_agg + (size_t)nc * 128 + h * 64);
        float4 x[16];
#pragma unroll
        for (int j = 0; j < 16; j++) x[j] = relu4(ap[j]);
        xwrite(sm, r, h, x);
    }
    __syncthreads();
    int warp = t >> 5, lane = t & 31;
    mma_stage<8, 64, LO_OFF>(sb, reinterpret_cast<const uint32_t*>(g_wo),
                             reinterpret_cast<const uint32_t*>(g_wo) + 8192,
                             reinterpret_cast<float*>(sm), warp, lane);
    if (v) {
        const float4* s4 = reinterpret_cast<const float4*>(
            reinterpret_cast<float*>(sm) + r * XSTRIDE + h * 64);
        const float4* bp = reinterpret_cast<const float4*>(bo + h * 64);
        int gid = gids[n];
        float* op = out + (size_t)gid * 128 + h * 64;
#pragma unroll
        for (int j = 0; j < 16; j++) {
            float4 s = s4[j], b = bp[j];
            float4 y = make_float4(fmaxf(s.x + b.x, 0.f), fmaxf(s.y + b.y, 0.f),
                                   fmaxf(s.z + b.z, 0.f), fmaxf(s.w + b.w, 0.f));
            red_add4(op + 4 * j, y);
        }
    }
}

extern "C" void kernel_launch(void* const* d_in, const int* in_sizes, int n_in,
                              void* d_out, int out_size) {
    const float* node_feat = (const float*)d_in[0];
    const float* edge_feat = (const float*)d_in[1];
    const float* Wn = (const float*)d_in[2];
    const float* bn = (const float*)d_in[3];
    const float* We = (const float*)d_in[4];
    const float* be = (const float*)d_in[5];
    const float* Wc = (const float*)d_in[6];
    const float* bc = (const float*)d_in[7];
    const float* Wo = (const float*)d_in[8];
    const float* bo = (const float*)d_in[9];
    const int* esrc = (const int*)d_in[10];
    const int* edst = (const int*)d_in[11];
    const int* gids = (const int*)d_in[12];
    float* out = (float*)d_out;

    cudaFuncSetAttribute(k_first, cudaFuncAttributeMaxDynamicSharedMemorySize, SMEM_BYTES);
    cudaFuncSetAttribute(k_iter,  cudaFuncAttributeMaxDynamicSharedMemorySize, SMEM_BYTES);
    cudaFuncSetAttribute(k_nlin,  cudaFuncAttributeMaxDynamicSharedMemorySize, SMEM_BYTES);
    cudaFuncSetAttribute(k_aggW,  cudaFuncAttributeMaxDynamicSharedMemorySize, SMEM_BYTES);
    cudaFuncSetAttribute(k_out,   cudaFuncAttributeMaxDynamicSharedMemorySize, SMEM_BYTES);

    const int NBN = (NN + 127) / 128;   // 391
    const int NBE = NE / 128;           // 6250

    k_zero<<<400, 256>>>(out, out_size);
    k_prep<<<64, 256>>>(Wc, Wn, Wo, We);
    k_nlin<<<NBN, 256, SMEM_BYTES>>>(node_feat, bn);
    k_first<<<NBE, 256, SMEM_BYTES>>>(edge_feat, be, nullptr, esrc, edst);
    for (int it = 0; it < 3; it++) {
        k_aggW<<<NBN, 256, SMEM_BYTES>>>();
        if (it < 2)
            k_iter<<<NBE, 256, SMEM_BYTES>>>(bc, esrc, edst);
        else
            k_last<<<NBE, 256>>>(bc, esrc, edst);
    }
    k_out<<<NBN, 256, SMEM_BYTES>>>(bo, gids, out);
}